// round 1
// baseline (speedup 1.0000x reference)
#include <cuda_runtime.h>

#define Bsz 64
#define Csz 256
#define HWsz 1024   // 32*32
#define CTR 528     // 16*32 + 16

// Scratch (device globals: no allocation allowed)
__device__ float g_dot[2][Bsz][HWsz];
__device__ float g_S[2][Bsz][Csz];
__device__ float g_P[2][Bsz][Csz];

// ---------------------------------------------------------------------------
// Kernel 0: zero the S/P accumulators
// ---------------------------------------------------------------------------
__global__ void zero_sp_kernel() {
    int i = blockIdx.x * blockDim.x + threadIdx.x;
    if (i < 2 * Bsz * Csz) {
        ((float*)g_S)[i] = 0.0f;
        ((float*)g_P)[i] = 0.0f;
    }
}

// ---------------------------------------------------------------------------
// Kernel 1: dot[b,hw] = (1/C) * sum_c x[b,c,hw] * x[b,c,center]
// grid: 128 (branch*64+b), block: 1024 threads (one per hw)
// ---------------------------------------------------------------------------
__global__ __launch_bounds__(1024) void dot_kernel(const float* __restrict__ x1,
                                                   const float* __restrict__ x2) {
    const int z = blockIdx.x;
    const int branch = z >> 6, b = z & 63;
    const float* xb = (branch ? x2 : x1) + (size_t)b * Csz * HWsz;

    __shared__ float cen[Csz];
    const int tid = threadIdx.x;
    if (tid < Csz) cen[tid] = xb[tid * HWsz + CTR];
    __syncthreads();

    float acc = 0.0f;
#pragma unroll 8
    for (int c = 0; c < Csz; ++c)
        acc += xb[c * HWsz + tid] * cen[c];
    g_dot[branch][b][tid] = acc * (1.0f / (float)Csz);
}

// ---------------------------------------------------------------------------
// Kernel 2: per-batch GEMM (256x1024x257) + fused sigmoid + fused pooling
//   attn[o,hw] = sigmoid( sum_c W[o,c]*x[c,hw] + W[o,256]*dot[hw] )
//   S[o] += sum_hw attn ; P[o] += sum_hw attn * x[o,hw]
// grid: (8 N-tiles, 2 M-tiles, 128 batch*branch), block: 256 threads
// Tile: BM=BN=128, BK=16, thread micro-tile 8x8.
// ---------------------------------------------------------------------------
__global__ __launch_bounds__(256) void gemm_pool_kernel(const float* __restrict__ x1,
                                                        const float* __restrict__ x2,
                                                        const float* __restrict__ w) {
    const int branch = blockIdx.z >> 6, b = blockIdx.z & 63;
    const float* xb = (branch ? x2 : x1) + (size_t)b * Csz * HWsz;
    const int m0 = blockIdx.y * 128;
    const int n0 = blockIdx.x * 128;

    __shared__ float As[16][128];   // As[k][m]
    __shared__ float Bs[16][128];   // Bs[k][n]

    const int tid = threadIdx.x;
    const int tx = tid & 15;        // N direction
    const int ty = tid >> 4;        // M direction

    // A-load mapping: each thread loads 8 consecutive k for one m row
    const int am = tid >> 1;
    const int ak = (tid & 1) * 8;
    // B-load mapping: each thread loads 8 consecutive n for one k row
    const int bkk = tid >> 4;
    const int bnn = (tid & 15) * 8;

    float acc[8][8];
#pragma unroll
    for (int i = 0; i < 8; ++i)
#pragma unroll
        for (int j = 0; j < 8; ++j) acc[i][j] = 0.0f;

    for (int k0 = 0; k0 < 256; k0 += 16) {
        // load A tile (conv_w rows m0..m0+127, cols k0..k0+15); row stride 257
        const float* wa = &w[(size_t)(m0 + am) * 257 + k0 + ak];
#pragma unroll
        for (int i = 0; i < 8; ++i) As[ak + i][am] = wa[i];

        // load B tile (x rows k0..k0+15, cols n0..n0+127), vectorized
        const float* xr = &xb[(size_t)(k0 + bkk) * HWsz + n0 + bnn];
        float4 v0 = *(const float4*)xr;
        float4 v1 = *(const float4*)(xr + 4);
        *(float4*)&Bs[bkk][bnn] = v0;
        *(float4*)&Bs[bkk][bnn + 4] = v1;
        __syncthreads();

#pragma unroll
        for (int kk = 0; kk < 16; ++kk) {
            float a[8], bb[8];
#pragma unroll
            for (int i = 0; i < 8; ++i) a[i] = As[kk][ty * 8 + i];
#pragma unroll
            for (int j = 0; j < 8; ++j) bb[j] = Bs[kk][tx * 8 + j];
#pragma unroll
            for (int i = 0; i < 8; ++i)
#pragma unroll
                for (int j = 0; j < 8; ++j) acc[i][j] += a[i] * bb[j];
        }
        __syncthreads();
    }

    // dot-column contribution (K index 256) + fused epilogue
    float wl[8], dv[8];
#pragma unroll
    for (int i = 0; i < 8; ++i) wl[i] = w[(size_t)(m0 + ty * 8 + i) * 257 + 256];
#pragma unroll
    for (int j = 0; j < 8; ++j) dv[j] = g_dot[branch][b][n0 + tx * 8 + j];

#pragma unroll
    for (int i = 0; i < 8; ++i) {
        const int row = m0 + ty * 8 + i;          // output channel o (0..255)
        const float* xr = &xb[(size_t)row * HWsz + n0 + tx * 8];
        float4 xv0 = *(const float4*)xr;
        float4 xv1 = *(const float4*)(xr + 4);
        float xv[8] = {xv0.x, xv0.y, xv0.z, xv0.w, xv1.x, xv1.y, xv1.z, xv1.w};

        float sS = 0.0f, sP = 0.0f;
#pragma unroll
        for (int j = 0; j < 8; ++j) {
            float v = acc[i][j] + wl[i] * dv[j];
            float attn = 1.0f / (1.0f + __expf(-v));
            sS += attn;
            sP += attn * xv[j];
        }
        // butterfly reduce across the 16 tx lanes (stays within 16-lane halves)
#pragma unroll
        for (int off = 8; off >= 1; off >>= 1) {
            sS += __shfl_xor_sync(0xffffffffu, sS, off);
            sP += __shfl_xor_sync(0xffffffffu, sP, off);
        }
        if (tx == 0) {
            atomicAdd(&g_S[branch][b][row], sS);
            atomicAdd(&g_P[branch][b][row], sP);
        }
    }
}

// ---------------------------------------------------------------------------
// Kernel 3: out[b,o] = P0/(S0+eps) + P1/(S1+eps)
// (caLayer softmax over a size-1 axis == 1.0, so branches simply add)
// ---------------------------------------------------------------------------
__global__ void finalize_kernel(float* __restrict__ out) {
    int i = blockIdx.x * blockDim.x + threadIdx.x;
    if (i < Bsz * Csz) {
        int b = i >> 8, o = i & 255;
        float r0 = g_P[0][b][o] / (g_S[0][b][o] + 1e-8f);
        float r1 = g_P[1][b][o] / (g_S[1][b][o] + 1e-8f);
        out[i] = r0 + r1;
    }
}

// ---------------------------------------------------------------------------
extern "C" void kernel_launch(void* const* d_in, const int* in_sizes, int n_in,
                              void* d_out, int out_size) {
    const float* x1 = (const float*)d_in[0];
    const float* x2 = (const float*)d_in[1];
    const float* w  = (const float*)d_in[2];
    // d_in[3..6] = ca_w1, ca_b1, ca_w2, ca_b2: mathematically unused
    // (softmax over size-1 axis is identically 1).
    float* out = (float*)d_out;

    zero_sp_kernel<<<(2 * Bsz * Csz + 255) / 256, 256>>>();
    dot_kernel<<<2 * Bsz, 1024>>>(x1, x2);
    gemm_pool_kernel<<<dim3(8, 2, 2 * Bsz), 256>>>(x1, x2, w);
    finalize_kernel<<<(Bsz * Csz + 255) / 256, 256>>>(out);
}

// round 3
// speedup vs baseline: 1.4978x; 1.4978x over previous
#include <cuda_runtime.h>
#include <cstdint>

#define Bsz  64
#define Csz  256
#define HW   1024
#define CTR  528        // 16*32 + 16
#define MT   128        // CTA M tile
#define NTc  256        // CTA N tile
#define KC   32         // K chunk
#define NCH  8          // 256 / 32
#define SA   136        // A smem row stride (floats), conflict-free
#define SB   264        // B smem row stride (floats), conflict-free

// per-(branch,batch) pooled sums; accumulated with atomics
__device__ float g_S[2 * Bsz][Csz];
__device__ float g_P[2 * Bsz][Csz];

__device__ __forceinline__ float tf32r(float f) {
    uint32_t u;
    asm("cvt.rna.tf32.f32 %0, %1;" : "=r"(u) : "f"(f));
    return __uint_as_float(u);
}

__device__ __forceinline__ void mma8(float* c, const float* a, float b0, float b1) {
    asm volatile(
        "mma.sync.aligned.m16n8k8.row.col.f32.tf32.tf32.f32 "
        "{%0,%1,%2,%3}, {%4,%5,%6,%7}, {%8,%9}, {%0,%1,%2,%3};"
        : "+f"(c[0]), "+f"(c[1]), "+f"(c[2]), "+f"(c[3])
        : "r"(__float_as_uint(a[0])), "r"(__float_as_uint(a[1])),
          "r"(__float_as_uint(a[2])), "r"(__float_as_uint(a[3])),
          "r"(__float_as_uint(b0)), "r"(__float_as_uint(b1)));
}

__global__ void zero_kernel() {
    int i = blockIdx.x * blockDim.x + threadIdx.x;
    if (i < 2 * Bsz * Csz) {
        ((float*)g_S)[i] = 0.0f;
        ((float*)g_P)[i] = 0.0f;
    }
}

// ---------------------------------------------------------------------------
// grid (4 n-tiles, 2 m-tiles, 128 z), block 256 (8 warps, 2x4 of 64x64 tiles)
// ---------------------------------------------------------------------------
__global__ void __launch_bounds__(256, 1)
gemm_pool_kernel(const float* __restrict__ x1, const float* __restrict__ x2,
                 const float* __restrict__ w) {
    extern __shared__ float sm[];
    float* cens = sm;                                   // 256
    float* Ab[2] = { sm + 256, sm + 256 + KC * SA };    // 2 x 4352
    float* Bb[2] = { sm + 256 + 2 * KC * SA,
                     sm + 256 + 2 * KC * SA + KC * SB };// 2 x 8448

    const int tid = threadIdx.x;
    const int z = blockIdx.z;
    const int branch = z >> 6, b = z & 63;
    const float* xz = (branch ? x2 : x1) + (size_t)b * Csz * HW;
    const int m0 = blockIdx.y * MT;
    const int n0 = blockIdx.x * NTc;

    cens[tid] = xz[(size_t)tid * HW + CTR] * (1.0f / 256.0f);
    __syncthreads();

    // ---- staging thread mappings
    const int am = tid >> 1;                 // A: row of W' (0..127)
    const int ak = (tid & 1) * 16;           // A: k half
    const float* wr = w + (size_t)(m0 + am) * 257;
    const float wl = wr[256];
    const int br_ = tid >> 3;                // B: k row (0..31)
    const int bc = (tid & 7) * 32;           // B: 32-col segment
    const float* xrow_base = xz + n0 + bc;

    float Ar[16];
    float4 Br[8];

#define LD_A(kc) { const float* p = wr + (kc) * KC + ak;                       \
    _Pragma("unroll") for (int u = 0; u < 16; ++u) Ar[u] = p[u]; }
#define LD_B(kc) { const float4* p = (const float4*)(xrow_base + (size_t)((kc) * KC + br_) * HW); \
    _Pragma("unroll") for (int q = 0; q < 8; ++q) Br[q] = p[q]; }
#define ST_A(buf, kc) { float* d = Ab[buf];                                    \
    _Pragma("unroll") for (int u = 0; u < 16; ++u)                             \
        d[(ak + u) * SA + am] = tf32r(Ar[u] + wl * cens[(kc) * KC + ak + u]); }
#define ST_B(buf) { float* d = Bb[buf] + br_ * SB + bc;                        \
    _Pragma("unroll") for (int q = 0; q < 8; ++q) {                            \
        d[4 * q + 0] = tf32r(Br[q].x); d[4 * q + 1] = tf32r(Br[q].y);          \
        d[4 * q + 2] = tf32r(Br[q].z); d[4 * q + 3] = tf32r(Br[q].w); } }

    // ---- MMA thread mappings
    const int lane = tid & 31;
    const int wid = tid >> 5;
    const int wm = (wid >> 2) * 64;          // warp M offset (0 / 64)
    const int wn = (wid & 3) * 64;           // warp N offset (0..192)
    const int g = lane >> 2, tg = lane & 3;

    float acc[4][8][4];
#pragma unroll
    for (int i = 0; i < 4; ++i)
#pragma unroll
        for (int j = 0; j < 8; ++j)
#pragma unroll
            for (int r = 0; r < 4; ++r) acc[i][j][r] = 0.0f;

    // prologue: stage chunk 0
    LD_A(0); LD_B(0); ST_A(0, 0); ST_B(0);
    __syncthreads();

    for (int kc = 0; kc < NCH; ++kc) {
        const int buf = kc & 1;
        if (kc < NCH - 1) { LD_A(kc + 1); LD_B(kc + 1); }

        const float* A = Ab[buf];
        const float* B = Bb[buf];
#pragma unroll
        for (int ks = 0; ks < 4; ++ks) {
            const int kb = ks * 8;
            float a[4][4];
#pragma unroll
            for (int i = 0; i < 4; ++i) {
                const int rb = wm + i * 16 + g;
                a[i][0] = A[(kb + tg) * SA + rb];
                a[i][1] = A[(kb + tg) * SA + rb + 8];
                a[i][2] = A[(kb + tg + 4) * SA + rb];
                a[i][3] = A[(kb + tg + 4) * SA + rb + 8];
            }
#pragma unroll
            for (int j = 0; j < 8; ++j) {
                const int cb = wn + j * 8 + g;
                float b0 = B[(kb + tg) * SB + cb];
                float b1 = B[(kb + tg + 4) * SB + cb];
#pragma unroll
                for (int i = 0; i < 4; ++i) mma8(acc[i][j], a[i], b0, b1);
            }
        }
        if (kc < NCH - 1) { ST_A(buf ^ 1, kc + 1); ST_B(buf ^ 1); }
        __syncthreads();
    }

    // ---- fused epilogue: sigmoid + pooled sums
#pragma unroll
    for (int i = 0; i < 4; ++i) {
        const int rb = m0 + wm + i * 16 + g;
#pragma unroll
        for (int rs = 0; rs < 2; ++rs) {
            const int row = rb + rs * 8;
            const float* xr = xz + (size_t)row * HW + n0 + wn + 2 * tg;
            float sS = 0.0f, sP = 0.0f;
#pragma unroll
            for (int j = 0; j < 8; ++j) {
                float v0 = acc[i][j][2 * rs];
                float v1 = acc[i][j][2 * rs + 1];
                float s0 = __fdividef(1.0f, 1.0f + __expf(-v0));
                float s1 = __fdividef(1.0f, 1.0f + __expf(-v1));
                float2 xv = *(const float2*)(xr + j * 8);
                sS += s0 + s1;
                sP += s0 * xv.x + s1 * xv.y;
            }
            sS += __shfl_xor_sync(0xffffffffu, sS, 1);
            sS += __shfl_xor_sync(0xffffffffu, sS, 2);
            sP += __shfl_xor_sync(0xffffffffu, sP, 1);
            sP += __shfl_xor_sync(0xffffffffu, sP, 2);
            if (tg == 0) {
                atomicAdd(&g_S[z][row], sS);
                atomicAdd(&g_P[z][row], sP);
            }
        }
    }
}

// ---------------------------------------------------------------------------
__global__ void finalize_kernel(float* __restrict__ out) {
    int i = blockIdx.x * blockDim.x + threadIdx.x;
    if (i < Bsz * Csz) {
        int b = i >> 8, o = i & 255;
        float r = 0.0f;
#pragma unroll
        for (int br = 0; br < 2; ++br) {
            int z = br * Bsz + b;
            r += g_P[z][o] / (g_S[z][o] + 1e-8f);
        }
        out[i] = r;
    }
}

// ---------------------------------------------------------------------------
extern "C" void kernel_launch(void* const* d_in, const int* in_sizes, int n_in,
                              void* d_out, int out_size) {
    const float* x1 = (const float*)d_in[0];
    const float* x2 = (const float*)d_in[1];
    const float* w  = (const float*)d_in[2];
    // d_in[3..6] (ca_*) are mathematically unused: softmax over a size-1 axis == 1.
    float* out = (float*)d_out;

    constexpr int SMEM_SZ = (256 + 2 * KC * SA + 2 * KC * SB) * 4;
    cudaFuncSetAttribute(gemm_pool_kernel,
                         cudaFuncAttributeMaxDynamicSharedMemorySize, SMEM_SZ);
    zero_kernel<<<(2 * Bsz * Csz + 255) / 256, 256>>>();
    gemm_pool_kernel<<<dim3(4, 2, 2 * Bsz), 256, SMEM_SZ>>>(x1, x2, w);
    finalize_kernel<<<(Bsz * Csz + 255) / 256, 256>>>(out);
}

// round 5
// speedup vs baseline: 2.0487x; 1.3678x over previous
#include <cuda_runtime.h>
#include <cstdint>

#define Bsz  64
#define Csz  256
#define HW   1024
#define CTR  528        // 16*32 + 16
#define KC   32         // K chunk
#define NCH  8          // 256 / 32
#define SA   136        // A smem k-row stride (floats)
#define SB   264        // B smem k-row stride (floats)

// per-CTA-per-warpcolumn partials: [z][ntile*4 + wncol][o]
// every slot has a unique writer -> no atomics, no zero pass
__device__ float g_S[2 * Bsz][16][Csz];
__device__ float g_P[2 * Bsz][16][Csz];

__device__ __forceinline__ float tf32r(float f) {
    uint32_t u;
    asm("cvt.rna.tf32.f32 %0, %1;" : "=r"(u) : "f"(f));
    return __uint_as_float(u);
}

__device__ __forceinline__ void mma8(float* c, const float* a, float b0, float b1) {
    asm volatile(
        "mma.sync.aligned.m16n8k8.row.col.f32.tf32.tf32.f32 "
        "{%0,%1,%2,%3}, {%4,%5,%6,%7}, {%8,%9}, {%0,%1,%2,%3};"
        : "+f"(c[0]), "+f"(c[1]), "+f"(c[2]), "+f"(c[3])
        : "r"(__float_as_uint(a[0])), "r"(__float_as_uint(a[1])),
          "r"(__float_as_uint(a[2])), "r"(__float_as_uint(a[3])),
          "r"(__float_as_uint(b0)), "r"(__float_as_uint(b1)));
}

// ---------------------------------------------------------------------------
// grid (4 n-tiles, 2 m-tiles, 128 z), block 512 (16 warps, 4x4 of 32x64 tiles)
// ---------------------------------------------------------------------------
__global__ void __launch_bounds__(512, 1)
gemm_pool_kernel(const float* __restrict__ x1, const float* __restrict__ x2,
                 const float* __restrict__ w) {
    extern __shared__ float sm[];
    float* cens = sm;                                    // 256
    float* Ab[2] = { sm + 256, sm + 256 + KC * SA };
    float* Bb[2] = { sm + 256 + 2 * KC * SA, sm + 256 + 2 * KC * SA + KC * SB };

    const int tid = threadIdx.x;
    const int z = blockIdx.z;
    const int branch = z >> 6, b = z & 63;
    const float* xz = (branch ? x2 : x1) + (size_t)b * Csz * HW;
    const int m0 = blockIdx.y * 128;
    const int n0 = blockIdx.x * 256;

    if (tid < 256) cens[tid] = xz[(size_t)tid * HW + CTR] * (1.0f / 256.0f);
    __syncthreads();

    // ---- A staging: lane-consecutive rows (STS conflict-free), 8 k's each
    const int am = tid & 127;                  // W' row within m-tile
    const int ag = tid >> 7;                   // k-octet 0..3
    const float* wr = w + (size_t)(m0 + am) * 257;
    const float wl = wr[256];
    // ---- B staging: 4 float4 per thread, fully sequential per warp
    //      idx = tid + q*512 -> row = idx>>6 (k-row), col4 = idx&63

    float Ar[8];
    float4 Br[4];

#define LD_A(kc) { const float* p = wr + (kc) * KC + ag * 8;                   \
    _Pragma("unroll") for (int u = 0; u < 8; ++u) Ar[u] = p[u]; }
#define LD_B(kc) {                                                             \
    _Pragma("unroll") for (int q = 0; q < 4; ++q) {                            \
        int idx = tid + q * 512;                                               \
        Br[q] = *(const float4*)(xz + (size_t)((kc) * KC + (idx >> 6)) * HW    \
                                  + n0 + (idx & 63) * 4); } }
#define ST_A(buf, kc) { float* d = Ab[buf];                                    \
    _Pragma("unroll") for (int u = 0; u < 8; ++u)                              \
        d[(ag * 8 + u) * SA + am] = tf32r(Ar[u] + wl * cens[(kc) * KC + ag * 8 + u]); }
#define ST_B(buf) {                                                            \
    _Pragma("unroll") for (int q = 0; q < 4; ++q) {                            \
        int idx = tid + q * 512;                                               \
        float4 v; v.x = tf32r(Br[q].x); v.y = tf32r(Br[q].y);                  \
        v.z = tf32r(Br[q].z); v.w = tf32r(Br[q].w);                            \
        *(float4*)(Bb[buf] + (idx >> 6) * SB + (idx & 63) * 4) = v; } }

    // ---- MMA mapping: 16 warps = 4 (M) x 4 (N); warp tile 32 x 64
    const int lane = tid & 31;
    const int wid = tid >> 5;
    const int wm = (wid >> 2) * 32;
    const int wn = (wid & 3) * 64;
    const int g = lane >> 2, tg = lane & 3;

    float acc[2][8][4];
#pragma unroll
    for (int i = 0; i < 2; ++i)
#pragma unroll
        for (int j = 0; j < 8; ++j)
#pragma unroll
            for (int r = 0; r < 4; ++r) acc[i][j][r] = 0.0f;

    LD_A(0); LD_B(0); ST_A(0, 0); ST_B(0);
    __syncthreads();

    for (int kc = 0; kc < NCH; ++kc) {
        const int buf = kc & 1;
        if (kc < NCH - 1) { LD_A(kc + 1); LD_B(kc + 1); }

        const float* A = Ab[buf];
        const float* B = Bb[buf];
#pragma unroll
        for (int ks = 0; ks < 4; ++ks) {
            const int kb = ks * 8;
            float a[2][4];
#pragma unroll
            for (int i = 0; i < 2; ++i) {
                const int rb = wm + i * 16 + g;
                a[i][0] = A[(kb + tg) * SA + rb];
                a[i][1] = A[(kb + tg) * SA + rb + 8];
                a[i][2] = A[(kb + tg + 4) * SA + rb];
                a[i][3] = A[(kb + tg + 4) * SA + rb + 8];
            }
#pragma unroll
            for (int j = 0; j < 8; ++j) {
                const int cb = wn + j * 8 + g;
                float b0 = B[(kb + tg) * SB + cb];
                float b1 = B[(kb + tg + 4) * SB + cb];
#pragma unroll
                for (int i = 0; i < 2; ++i) mma8(acc[i][j], a[i], b0, b1);
            }
        }
        if (kc < NCH - 1) { ST_A(buf ^ 1, kc + 1); ST_B(buf ^ 1); }
        __syncthreads();
    }

    // ---- fused epilogue: sigmoid + pooled partials (unique slot per warp-col)
    const int slot = blockIdx.x * 4 + (wid & 3);
#pragma unroll
    for (int i = 0; i < 2; ++i) {
#pragma unroll
        for (int rs = 0; rs < 2; ++rs) {
            const int row = m0 + wm + i * 16 + g + rs * 8;
            const float* xr = xz + (size_t)row * HW + n0 + wn + 2 * tg;
            float sS = 0.0f, sP = 0.0f;
#pragma unroll
            for (int j = 0; j < 8; ++j) {
                float v0 = acc[i][j][2 * rs];
                float v1 = acc[i][j][2 * rs + 1];
                float s0 = __fdividef(1.0f, 1.0f + __expf(-v0));
                float s1 = __fdividef(1.0f, 1.0f + __expf(-v1));
                float2 xv = *(const float2*)(xr + j * 8);
                sS += s0 + s1;
                sP += s0 * xv.x + s1 * xv.y;
            }
            sS += __shfl_xor_sync(0xffffffffu, sS, 1);
            sS += __shfl_xor_sync(0xffffffffu, sS, 2);
            sP += __shfl_xor_sync(0xffffffffu, sP, 1);
            sP += __shfl_xor_sync(0xffffffffu, sP, 2);
            if (tg == 0) {
                g_S[z][slot][row] = sS;
                g_P[z][slot][row] = sP;
            }
        }
    }
}

// ---------------------------------------------------------------------------
__global__ void finalize_kernel(float* __restrict__ out) {
    int i = blockIdx.x * blockDim.x + threadIdx.x;
    if (i < Bsz * Csz) {
        int b = i >> 8, o = i & 255;
        float r = 0.0f;
#pragma unroll
        for (int br = 0; br < 2; ++br) {
            int z = br * Bsz + b;
            float S = 0.0f, P = 0.0f;
#pragma unroll
            for (int s = 0; s < 16; ++s) {
                S += g_S[z][s][o];
                P += g_P[z][s][o];
            }
            r += P / (S + 1e-8f);
        }
        out[i] = r;
    }
}

// ---------------------------------------------------------------------------
extern "C" void kernel_launch(void* const* d_in, const int* in_sizes, int n_in,
                              void* d_out, int out_size) {
    const float* x1 = (const float*)d_in[0];
    const float* x2 = (const float*)d_in[1];
    const float* w  = (const float*)d_in[2];
    // d_in[3..6] (ca_*) are mathematically unused: softmax over a size-1 axis == 1.
    float* out = (float*)d_out;

    constexpr int SMEM_SZ = (256 + 2 * KC * SA + 2 * KC * SB) * 4;
    cudaFuncSetAttribute(gemm_pool_kernel,
                         cudaFuncAttributeMaxDynamicSharedMemorySize, SMEM_SZ);
    gemm_pool_kernel<<<dim3(4, 2, 2 * Bsz), 512, SMEM_SZ>>>(x1, x2, w);
    finalize_kernel<<<(Bsz * Csz + 255) / 256, 256>>>(out);
}

// round 6
// speedup vs baseline: 2.6359x; 1.2866x over previous
#include <cuda_runtime.h>
#include <cstdint>

#define Bsz  64
#define Csz  256
#define HW   1024
#define CTR  528        // 16*32 + 16
#define KC   32         // K chunk
#define NCH  8          // 256 / 32
#define SA   136        // A smem k-row stride (floats)
#define SB   264        // B smem k-row stride (floats)

// per-CTA-per-warpcolumn partials: [z][ntile*4 + wncol][o]
__device__ float g_S[2 * Bsz][16][Csz];
__device__ float g_P[2 * Bsz][16][Csz];

// transposed weights and per-z folded A operand (k-major, tf32-converted)
__device__ float g_Wt[257][Csz];
__device__ float g_Wzt[2 * Bsz][Csz][Csz];   // 33.5 MB

__device__ __forceinline__ float tf32r(float f) {
    uint32_t u;
    asm("cvt.rna.tf32.f32 %0, %1;" : "=r"(u) : "f"(f));
    return __uint_as_float(u);
}

__device__ __forceinline__ void mma8(float* c, const float* a, float b0, float b1) {
    asm volatile(
        "mma.sync.aligned.m16n8k8.row.col.f32.tf32.tf32.f32 "
        "{%0,%1,%2,%3}, {%4,%5,%6,%7}, {%8,%9}, {%0,%1,%2,%3};"
        : "+f"(c[0]), "+f"(c[1]), "+f"(c[2]), "+f"(c[3])
        : "r"(__float_as_uint(a[0])), "r"(__float_as_uint(a[1])),
          "r"(__float_as_uint(a[2])), "r"(__float_as_uint(a[3])),
          "r"(__float_as_uint(b0)), "r"(__float_as_uint(b1)));
}

// ---------------------------------------------------------------------------
// prep 1: Wt[k][m] = W[m][k]   (tiny one-time transpose)
// ---------------------------------------------------------------------------
__global__ void transpose_w(const float* __restrict__ w) {
    int k = blockIdx.x;          // 0..256
    int m = threadIdx.x;         // 0..255
    g_Wt[k][m] = w[(size_t)m * 257 + k];
}

// ---------------------------------------------------------------------------
// prep 2: Wzt[z][k][m] = tf32(Wt[k][m] + Wt[256][m] * x_z[k][CTR]/256)
// grid (16, 128), block 1024: idx = blockIdx.x*1024+tid in [0,16384) float4s
// ---------------------------------------------------------------------------
__global__ void __launch_bounds__(1024) build_wzt(const float* __restrict__ x1,
                                                  const float* __restrict__ x2) {
    const int z = blockIdx.y;
    const int branch = z >> 6, b = z & 63;
    const float* xz = (branch ? x2 : x1) + (size_t)b * Csz * HW;

    int idx = blockIdx.x * 1024 + threadIdx.x;   // float4 index
    int k = idx >> 6;                             // 64 float4 per k row
    int m4 = (idx & 63) * 4;
    float cen = xz[(size_t)k * HW + CTR] * (1.0f / 256.0f);
    float4 wt = *(const float4*)&g_Wt[k][m4];
    float4 wc = *(const float4*)&g_Wt[256][m4];
    float4 r;
    r.x = tf32r(wt.x + wc.x * cen);
    r.y = tf32r(wt.y + wc.y * cen);
    r.z = tf32r(wt.z + wc.z * cen);
    r.w = tf32r(wt.w + wc.w * cen);
    *(float4*)&g_Wzt[z][k][m4] = r;
}

// ---------------------------------------------------------------------------
// main GEMM + fused sigmoid-pool
// grid (4 n-tiles, 2 m-tiles, 128 z), block 512 (16 warps, 4x4 of 32x64 tiles)
// ---------------------------------------------------------------------------
__global__ void __launch_bounds__(512, 1)
gemm_pool_kernel(const float* __restrict__ x1, const float* __restrict__ x2) {
    extern __shared__ float sm[];
    float* Ab[2] = { sm, sm + KC * SA };
    float* Bb[2] = { sm + 2 * KC * SA, sm + 2 * KC * SA + KC * SB };

    const int tid = threadIdx.x;
    const int z = blockIdx.z;
    const int branch = z >> 6, b = z & 63;
    const float* xz = (branch ? x2 : x1) + (size_t)b * Csz * HW;
    const int m0 = blockIdx.y * 128;
    const int n0 = blockIdx.x * 256;
    const float* wzt = &g_Wzt[z][0][0];   // [256][256] k-major, tf32-ready

    float4 Ar[2];
    float4 Br[4];

    // A: 2 float4/thread, coalesced; each warp fills one 128-float k-row seg
#define LD_A(kc) { _Pragma("unroll") for (int q = 0; q < 2; ++q) {             \
        int idx = tid + q * 512;                                               \
        Ar[q] = *(const float4*)(wzt + (size_t)((kc) * KC + (idx >> 5)) * 256  \
                                 + m0 + (idx & 31) * 4); } }
#define ST_A(buf) { _Pragma("unroll") for (int q = 0; q < 2; ++q) {            \
        int idx = tid + q * 512;                                               \
        *(float4*)(Ab[buf] + (idx >> 5) * SA + (idx & 31) * 4) = Ar[q]; } }
    // B: 4 float4/thread, coalesced
#define LD_B(kc) { _Pragma("unroll") for (int q = 0; q < 4; ++q) {             \
        int idx = tid + q * 512;                                               \
        Br[q] = *(const float4*)(xz + (size_t)((kc) * KC + (idx >> 6)) * HW    \
                                 + n0 + (idx & 63) * 4); } }
#define ST_B(buf) { _Pragma("unroll") for (int q = 0; q < 4; ++q) {            \
        int idx = tid + q * 512;                                               \
        float4 v; v.x = tf32r(Br[q].x); v.y = tf32r(Br[q].y);                  \
        v.z = tf32r(Br[q].z); v.w = tf32r(Br[q].w);                            \
        *(float4*)(Bb[buf] + (idx >> 6) * SB + (idx & 63) * 4) = v; } }

    // ---- MMA mapping: 16 warps = 4 (M) x 4 (N); warp tile 32 x 64
    const int lane = tid & 31;
    const int wid = tid >> 5;
    const int wm = (wid >> 2) * 32;
    const int wn = (wid & 3) * 64;
    const int g = lane >> 2, tg = lane & 3;

    float acc[2][8][4];
#pragma unroll
    for (int i = 0; i < 2; ++i)
#pragma unroll
        for (int j = 0; j < 8; ++j)
#pragma unroll
            for (int r = 0; r < 4; ++r) acc[i][j][r] = 0.0f;

    LD_A(0); LD_B(0); ST_A(0); ST_B(0);
    __syncthreads();

    for (int kc = 0; kc < NCH; ++kc) {
        const int buf = kc & 1;
        if (kc < NCH - 1) { LD_A(kc + 1); LD_B(kc + 1); }

        const float* A = Ab[buf];
        const float* B = Bb[buf];
#pragma unroll
        for (int ks = 0; ks < 4; ++ks) {
            const int kb = ks * 8;
            float a[2][4];
#pragma unroll
            for (int i = 0; i < 2; ++i) {
                const int rb = wm + i * 16 + g;
                a[i][0] = A[(kb + tg) * SA + rb];
                a[i][1] = A[(kb + tg) * SA + rb + 8];
                a[i][2] = A[(kb + tg + 4) * SA + rb];
                a[i][3] = A[(kb + tg + 4) * SA + rb + 8];
            }
#pragma unroll
            for (int j = 0; j < 8; ++j) {
                const int cb = wn + j * 8 + g;
                float b0 = B[(kb + tg) * SB + cb];
                float b1 = B[(kb + tg + 4) * SB + cb];
#pragma unroll
                for (int i = 0; i < 2; ++i) mma8(acc[i][j], a[i], b0, b1);
            }
        }
        if (kc < NCH - 1) { ST_A(buf ^ 1); ST_B(buf ^ 1); }
        __syncthreads();
    }

    // ---- fused epilogue: sigmoid + pooled partials (unique slot per warp-col)
    const int slot = blockIdx.x * 4 + (wid & 3);
#pragma unroll
    for (int i = 0; i < 2; ++i) {
#pragma unroll
        for (int rs = 0; rs < 2; ++rs) {
            const int row = m0 + wm + i * 16 + g + rs * 8;
            const float* xr = xz + (size_t)row * HW + n0 + wn + 2 * tg;
            float sS = 0.0f, sP = 0.0f;
#pragma unroll
            for (int j = 0; j < 8; ++j) {
                float v0 = acc[i][j][2 * rs];
                float v1 = acc[i][j][2 * rs + 1];
                float s0 = __fdividef(1.0f, 1.0f + __expf(-v0));
                float s1 = __fdividef(1.0f, 1.0f + __expf(-v1));
                float2 xv = *(const float2*)(xr + j * 8);
                sS += s0 + s1;
                sP += s0 * xv.x + s1 * xv.y;
            }
            sS += __shfl_xor_sync(0xffffffffu, sS, 1);
            sS += __shfl_xor_sync(0xffffffffu, sS, 2);
            sP += __shfl_xor_sync(0xffffffffu, sP, 1);
            sP += __shfl_xor_sync(0xffffffffu, sP, 2);
            if (tg == 0) {
                g_S[z][slot][row] = sS;
                g_P[z][slot][row] = sP;
            }
        }
    }
}

// ---------------------------------------------------------------------------
__global__ void finalize_kernel(float* __restrict__ out) {
    int i = blockIdx.x * blockDim.x + threadIdx.x;
    if (i < Bsz * Csz) {
        int b = i >> 8, o = i & 255;
        float r = 0.0f;
#pragma unroll
        for (int br = 0; br < 2; ++br) {
            int z = br * Bsz + b;
            float S = 0.0f, P = 0.0f;
#pragma unroll
            for (int s = 0; s < 16; ++s) {
                S += g_S[z][s][o];
                P += g_P[z][s][o];
            }
            r += P / (S + 1e-8f);
        }
        out[i] = r;
    }
}

// ---------------------------------------------------------------------------
extern "C" void kernel_launch(void* const* d_in, const int* in_sizes, int n_in,
                              void* d_out, int out_size) {
    const float* x1 = (const float*)d_in[0];
    const float* x2 = (const float*)d_in[1];
    const float* w  = (const float*)d_in[2];
    // d_in[3..6] (ca_*) are mathematically unused: softmax over a size-1 axis == 1.
    float* out = (float*)d_out;

    constexpr int SMEM_SZ = (2 * KC * SA + 2 * KC * SB) * 4;
    cudaFuncSetAttribute(gemm_pool_kernel,
                         cudaFuncAttributeMaxDynamicSharedMemorySize, SMEM_SZ);

    transpose_w<<<257, 256>>>(w);
    build_wzt<<<dim3(16, 2 * Bsz), 1024>>>(x1, x2);
    gemm_pool_kernel<<<dim3(4, 2, 2 * Bsz), 512, SMEM_SZ>>>(x1, x2);
    finalize_kernel<<<(Bsz * Csz + 255) / 256, 256>>>(out);
}

// round 7
// speedup vs baseline: 3.3971x; 1.2888x over previous
#include <cuda_runtime.h>
#include <cstdint>

#define Bsz  64
#define Csz  256
#define HW   1024
#define CTR  528        // 16*32 + 16
#define KC   32         // K chunk (= 16 fp16x2 k-pairs)
#define NCH  8          // 256 / 32
#define SA2  136        // A smem k2-row stride (u32)
#define SB2  264        // B smem k2-row stride (u32)

// per-CTA-per-warpcolumn partials: [z][ntile*4 + wncol][o]
__device__ float g_S[2 * Bsz][16][Csz];
__device__ float g_P[2 * Bsz][16][Csz];

// transposed weights; per-z folded A operand packed as fp16x2 over k-pairs
__device__ float    g_Wt[257][Csz];
__device__ uint32_t g_Wzh[2 * Bsz][Csz / 2][Csz];   // 16.8 MB

__device__ __forceinline__ uint32_t packf16(float lo, float hi) {
    uint32_t d;
    asm("cvt.rn.f16x2.f32 %0, %1, %2;" : "=r"(d) : "f"(hi), "f"(lo));
    return d;
}

__device__ __forceinline__ void mma16(float* c, const uint32_t* a,
                                      uint32_t b0, uint32_t b1) {
    asm volatile(
        "mma.sync.aligned.m16n8k16.row.col.f32.f16.f16.f32 "
        "{%0,%1,%2,%3}, {%4,%5,%6,%7}, {%8,%9}, {%0,%1,%2,%3};"
        : "+f"(c[0]), "+f"(c[1]), "+f"(c[2]), "+f"(c[3])
        : "r"(a[0]), "r"(a[1]), "r"(a[2]), "r"(a[3]), "r"(b0), "r"(b1));
}

// ---------------------------------------------------------------------------
// prep 1: Wt[k][m] = W[m][k]
// ---------------------------------------------------------------------------
__global__ void transpose_w(const float* __restrict__ w) {
    int k = blockIdx.x;          // 0..256
    int m = threadIdx.x;         // 0..255
    g_Wt[k][m] = w[(size_t)m * 257 + k];
}

// ---------------------------------------------------------------------------
// prep 2: Wzh[z][k2][m] = fp16x2( Wt[2k2][m]+wc[m]*cen(2k2),
//                                 Wt[2k2+1][m]+wc[m]*cen(2k2+1) )
// grid (32, 128), block 1024: idx in [0, 32768) u32 per z
// ---------------------------------------------------------------------------
__global__ void __launch_bounds__(1024) build_wzh(const float* __restrict__ x1,
                                                  const float* __restrict__ x2) {
    const int z = blockIdx.y;
    const int branch = z >> 6, b = z & 63;
    const float* xz = (branch ? x2 : x1) + (size_t)b * Csz * HW;

    int idx = blockIdx.x * 1024 + threadIdx.x;
    int m = idx & 255;
    int k2 = idx >> 8;                            // 0..127
    float cen0 = xz[(size_t)(2 * k2) * HW + CTR] * (1.0f / 256.0f);
    float cen1 = xz[(size_t)(2 * k2 + 1) * HW + CTR] * (1.0f / 256.0f);
    float wc = g_Wt[256][m];
    float v0 = g_Wt[2 * k2][m] + wc * cen0;
    float v1 = g_Wt[2 * k2 + 1][m] + wc * cen1;
    g_Wzh[z][k2][m] = packf16(v0, v1);
}

// ---------------------------------------------------------------------------
// main GEMM (fp16 in, fp32 acc) + fused sigmoid-pool
// grid (4 n-tiles, 2 m-tiles, 128 z), block 512 (16 warps, 4x4 of 32x64 tiles)
// ---------------------------------------------------------------------------
__global__ void __launch_bounds__(512, 1)
gemm_pool_kernel(const float* __restrict__ x1, const float* __restrict__ x2) {
    extern __shared__ uint32_t sm[];
    uint32_t* Ab[2] = { sm, sm + 16 * SA2 };
    uint32_t* Bb[2] = { sm + 2 * 16 * SA2, sm + 2 * 16 * SA2 + 16 * SB2 };

    const int tid = threadIdx.x;
    const int z = blockIdx.z;
    const int branch = z >> 6, b = z & 63;
    const float* xz = (branch ? x2 : x1) + (size_t)b * Csz * HW;
    const int m0 = blockIdx.y * 128;
    const int n0 = blockIdx.x * 256;
    const uint32_t* wzh = &g_Wzh[z][0][0];   // [128 k2][256 m]

    uint4 Ar;
    float4 Brf[2][2];

    // A: 1 uint4/thread (copy, already fp16x2): k2 = tid>>5, m4 = (tid&31)*4
#define LD_A(kc) { Ar = *(const uint4*)(wzh + (size_t)((kc) * 16 + (tid >> 5)) * 256 \
                                        + m0 + (tid & 31) * 4); }
#define ST_A(buf) { *(uint4*)(Ab[buf] + (tid >> 5) * SA2 + (tid & 31) * 4) = Ar; }
    // B: 2 k-rows per thread -> pack; idx = tid + q*512: k2 = idx>>6, n4=(idx&63)*4
#define LD_B(kc) { _Pragma("unroll") for (int q = 0; q < 2; ++q) {             \
        int idx = tid + q * 512;                                               \
        const float* p0 = xz + (size_t)((kc) * KC + 2 * (idx >> 6)) * HW       \
                          + n0 + (idx & 63) * 4;                               \
        Brf[q][0] = *(const float4*)p0;                                        \
        Brf[q][1] = *(const float4*)(p0 + HW); } }
#define ST_B(buf) { _Pragma("unroll") for (int q = 0; q < 2; ++q) {            \
        int idx = tid + q * 512;                                               \
        uint4 v;                                                               \
        v.x = packf16(Brf[q][0].x, Brf[q][1].x);                               \
        v.y = packf16(Brf[q][0].y, Brf[q][1].y);                               \
        v.z = packf16(Brf[q][0].z, Brf[q][1].z);                               \
        v.w = packf16(Brf[q][0].w, Brf[q][1].w);                               \
        *(uint4*)(Bb[buf] + (idx >> 6) * SB2 + (idx & 63) * 4) = v; } }

    // ---- MMA mapping: 16 warps = 4 (M) x 4 (N); warp tile 32 x 64
    const int lane = tid & 31;
    const int wid = tid >> 5;
    const int wm = (wid >> 2) * 32;
    const int wn = (wid & 3) * 64;
    const int g = lane >> 2, tg = lane & 3;

    float acc[2][8][4];
#pragma unroll
    for (int i = 0; i < 2; ++i)
#pragma unroll
        for (int j = 0; j < 8; ++j)
#pragma unroll
            for (int r = 0; r < 4; ++r) acc[i][j][r] = 0.0f;

    LD_A(0); LD_B(0); ST_A(0); ST_B(0);
    __syncthreads();

    for (int kc = 0; kc < NCH; ++kc) {
        const int buf = kc & 1;
        if (kc < NCH - 1) { LD_A(kc + 1); LD_B(kc + 1); }

        const uint32_t* A = Ab[buf];
        const uint32_t* B = Bb[buf];
#pragma unroll
        for (int ks = 0; ks < 2; ++ks) {
            const int ko = ks * 8;                 // k2 offset (8 pairs = k16)
            uint32_t a[2][4];
#pragma unroll
            for (int i = 0; i < 2; ++i) {
                const int rb = wm + i * 16 + g;
                a[i][0] = A[(ko + tg) * SA2 + rb];
                a[i][1] = A[(ko + tg) * SA2 + rb + 8];
                a[i][2] = A[(ko + tg + 4) * SA2 + rb];
                a[i][3] = A[(ko + tg + 4) * SA2 + rb + 8];
            }
#pragma unroll
            for (int j = 0; j < 8; ++j) {
                const int cb = wn + j * 8 + g;
                uint32_t b0 = B[(ko + tg) * SB2 + cb];
                uint32_t b1 = B[(ko + tg + 4) * SB2 + cb];
#pragma unroll
                for (int i = 0; i < 2; ++i) mma16(acc[i][j], a[i], b0, b1);
            }
        }
        if (kc < NCH - 1) { ST_A(buf ^ 1); ST_B(buf ^ 1); }
        __syncthreads();
    }

    // ---- fused epilogue: sigmoid + pooled partials (unique slot per warp-col)
    const int slot = blockIdx.x * 4 + (wid & 3);
#pragma unroll
    for (int i = 0; i < 2; ++i) {
#pragma unroll
        for (int rs = 0; rs < 2; ++rs) {
            const int row = m0 + wm + i * 16 + g + rs * 8;
            const float* xr = xz + (size_t)row * HW + n0 + wn + 2 * tg;
            float sS = 0.0f, sP = 0.0f;
#pragma unroll
            for (int j = 0; j < 8; ++j) {
                float v0 = acc[i][j][2 * rs];
                float v1 = acc[i][j][2 * rs + 1];
                float s0 = __fdividef(1.0f, 1.0f + __expf(-v0));
                float s1 = __fdividef(1.0f, 1.0f + __expf(-v1));
                float2 xv = *(const float2*)(xr + j * 8);
                sS += s0 + s1;
                sP += s0 * xv.x + s1 * xv.y;
            }
            sS += __shfl_xor_sync(0xffffffffu, sS, 1);
            sS += __shfl_xor_sync(0xffffffffu, sS, 2);
            sP += __shfl_xor_sync(0xffffffffu, sP, 1);
            sP += __shfl_xor_sync(0xffffffffu, sP, 2);
            if (tg == 0) {
                g_S[z][slot][row] = sS;
                g_P[z][slot][row] = sP;
            }
        }
    }
}

// ---------------------------------------------------------------------------
__global__ void finalize_kernel(float* __restrict__ out) {
    int i = blockIdx.x * blockDim.x + threadIdx.x;
    if (i < Bsz * Csz) {
        int b = i >> 8, o = i & 255;
        float r = 0.0f;
#pragma unroll
        for (int br = 0; br < 2; ++br) {
            int z = br * Bsz + b;
            float S = 0.0f, P = 0.0f;
#pragma unroll
            for (int s = 0; s < 16; ++s) {
                S += g_S[z][s][o];
                P += g_P[z][s][o];
            }
            r += P / (S + 1e-8f);
        }
        out[i] = r;
    }
}

// ---------------------------------------------------------------------------
extern "C" void kernel_launch(void* const* d_in, const int* in_sizes, int n_in,
                              void* d_out, int out_size) {
    const float* x1 = (const float*)d_in[0];
    const float* x2 = (const float*)d_in[1];
    const float* w  = (const float*)d_in[2];
    // d_in[3..6] (ca_*) are mathematically unused: softmax over a size-1 axis == 1.
    float* out = (float*)d_out;

    constexpr int SMEM_SZ = (2 * 16 * SA2 + 2 * 16 * SB2) * 4;   // 51200 B
    cudaFuncSetAttribute(gemm_pool_kernel,
                         cudaFuncAttributeMaxDynamicSharedMemorySize, SMEM_SZ);

    transpose_w<<<257, 256>>>(w);
    build_wzh<<<dim3(32, 2 * Bsz), 1024>>>(x1, x2);
    gemm_pool_kernel<<<dim3(4, 2, 2 * Bsz), 512, SMEM_SZ>>>(x1, x2);
    finalize_kernel<<<(Bsz * Csz + 255) / 256, 256>>>(out);
}

// round 8
// speedup vs baseline: 3.8698x; 1.1392x over previous
#include <cuda_runtime.h>
#include <cstdint>

#define Bsz  64
#define Csz  256
#define HW   1024
#define CTR  528        // 16*32 + 16
#define KC   32         // K chunk (= 16 fp16x2 k-pairs)
#define NCH  8          // 256 / 32
#define SA2  136        // A smem k2-row stride (u32), 128 + 8 pad
#define SB2  136        // B smem k2-row stride (u32), 128 + 8 pad

// per-CTA-per-warpcolumn partials: [z][ntile*2 + wncol][o]  (16 slots)
__device__ float g_S[2 * Bsz][16][Csz];
__device__ float g_P[2 * Bsz][16][Csz];

// transposed weights; per-z folded A operand packed as fp16x2 over k-pairs
__device__ float    g_Wt[257][Csz];
__device__ uint32_t g_Wzh[2 * Bsz][Csz / 2][Csz];   // 16.8 MB

__device__ __forceinline__ uint32_t packf16(float lo, float hi) {
    uint32_t d;
    asm("cvt.rn.f16x2.f32 %0, %1, %2;" : "=r"(d) : "f"(hi), "f"(lo));
    return d;
}

__device__ __forceinline__ void mma16(float* c, const uint32_t* a,
                                      uint32_t b0, uint32_t b1) {
    asm volatile(
        "mma.sync.aligned.m16n8k16.row.col.f32.f16.f16.f32 "
        "{%0,%1,%2,%3}, {%4,%5,%6,%7}, {%8,%9}, {%0,%1,%2,%3};"
        : "+f"(c[0]), "+f"(c[1]), "+f"(c[2]), "+f"(c[3])
        : "r"(a[0]), "r"(a[1]), "r"(a[2]), "r"(a[3]), "r"(b0), "r"(b1));
}

// ---------------------------------------------------------------------------
// prep 1: Wt[k][m] = W[m][k]
// ---------------------------------------------------------------------------
__global__ void transpose_w(const float* __restrict__ w) {
    int k = blockIdx.x;          // 0..256
    int m = threadIdx.x;         // 0..255
    g_Wt[k][m] = w[(size_t)m * 257 + k];
}

// ---------------------------------------------------------------------------
// prep 2: Wzh[z][k2][m] = fp16x2 of the two folded k values
// ---------------------------------------------------------------------------
__global__ void __launch_bounds__(1024) build_wzh(const float* __restrict__ x1,
                                                  const float* __restrict__ x2) {
    const int z = blockIdx.y;
    const int branch = z >> 6, b = z & 63;
    const float* xz = (branch ? x2 : x1) + (size_t)b * Csz * HW;

    int idx = blockIdx.x * 1024 + threadIdx.x;
    int m = idx & 255;
    int k2 = idx >> 8;                            // 0..127
    float cen0 = xz[(size_t)(2 * k2) * HW + CTR] * (1.0f / 256.0f);
    float cen1 = xz[(size_t)(2 * k2 + 1) * HW + CTR] * (1.0f / 256.0f);
    float wc = g_Wt[256][m];
    float v0 = g_Wt[2 * k2][m] + wc * cen0;
    float v1 = g_Wt[2 * k2 + 1][m] + wc * cen1;
    g_Wzh[z][k2][m] = packf16(v0, v1);
}

// ---------------------------------------------------------------------------
// main GEMM (fp16 in, fp32 acc) + fused sigmoid-pool
// grid (8 n-tiles, 2 m-tiles, 128 z), block 256 (8 warps = 4M x 2N, 32x64 each)
// 2 CTAs co-resident per SM -> sync/staging/tail bubbles overlap.
// ---------------------------------------------------------------------------
__global__ void __launch_bounds__(256, 2)
gemm_pool_kernel(const float* __restrict__ x1, const float* __restrict__ x2) {
    extern __shared__ uint32_t sm[];
    uint32_t* Ab[2] = { sm, sm + 16 * SA2 };
    uint32_t* Bb[2] = { sm + 2 * 16 * SA2, sm + 2 * 16 * SA2 + 16 * SB2 };

    const int tid = threadIdx.x;
    const int z = blockIdx.z;
    const int branch = z >> 6, b = z & 63;
    const float* xz = (branch ? x2 : x1) + (size_t)b * Csz * HW;
    const int m0 = blockIdx.y * 128;
    const int n0 = blockIdx.x * 128;
    const uint32_t* wzh = &g_Wzh[z][0][0];   // [128 k2][256 m]

    uint4 Ar[2];
    float4 Brf[2][2];

    // A: 2 uint4/thread (pure copy): idx = tid + q*256 -> k2 = idx>>5, m4=(idx&31)*4
#define LD_A(kc) { _Pragma("unroll") for (int q = 0; q < 2; ++q) {             \
        int idx = tid + q * 256;                                               \
        Ar[q] = *(const uint4*)(wzh + (size_t)((kc) * 16 + (idx >> 5)) * 256   \
                                + m0 + (idx & 31) * 4); } }
#define ST_A(buf) { _Pragma("unroll") for (int q = 0; q < 2; ++q) {            \
        int idx = tid + q * 256;                                               \
        *(uint4*)(Ab[buf] + (idx >> 5) * SA2 + (idx & 31) * 4) = Ar[q]; } }
    // B: 2 k-rows packed per u32; idx = tid + q*256: k2 = idx>>5, n4=(idx&31)*4
#define LD_B(kc) { _Pragma("unroll") for (int q = 0; q < 2; ++q) {             \
        int idx = tid + q * 256;                                               \
        const float* p0 = xz + (size_t)((kc) * KC + 2 * (idx >> 5)) * HW       \
                          + n0 + (idx & 31) * 4;                               \
        Brf[q][0] = *(const float4*)p0;                                        \
        Brf[q][1] = *(const float4*)(p0 + HW); } }
#define ST_B(buf) { _Pragma("unroll") for (int q = 0; q < 2; ++q) {            \
        int idx = tid + q * 256;                                               \
        uint4 v;                                                               \
        v.x = packf16(Brf[q][0].x, Brf[q][1].x);                               \
        v.y = packf16(Brf[q][0].y, Brf[q][1].y);                               \
        v.z = packf16(Brf[q][0].z, Brf[q][1].z);                               \
        v.w = packf16(Brf[q][0].w, Brf[q][1].w);                               \
        *(uint4*)(Bb[buf] + (idx >> 5) * SB2 + (idx & 31) * 4) = v; } }

    // ---- MMA mapping: 8 warps = 4 (M) x 2 (N); warp tile 32 x 64
    const int lane = tid & 31;
    const int wid = tid >> 5;
    const int wm = (wid >> 1) * 32;
    const int wn = (wid & 1) * 64;
    const int g = lane >> 2, tg = lane & 3;

    float acc[2][8][4];
#pragma unroll
    for (int i = 0; i < 2; ++i)
#pragma unroll
        for (int j = 0; j < 8; ++j)
#pragma unroll
            for (int r = 0; r < 4; ++r) acc[i][j][r] = 0.0f;

    LD_A(0); LD_B(0); ST_A(0); ST_B(0);
    __syncthreads();

    for (int kc = 0; kc < NCH; ++kc) {
        const int buf = kc & 1;
        if (kc < NCH - 1) { LD_A(kc + 1); LD_B(kc + 1); }

        const uint32_t* A = Ab[buf];
        const uint32_t* B = Bb[buf];
#pragma unroll
        for (int ks = 0; ks < 2; ++ks) {
            const int ko = ks * 8;                 // k2 offset (8 pairs = k16)
            uint32_t a[2][4];
#pragma unroll
            for (int i = 0; i < 2; ++i) {
                const int rb = wm + i * 16 + g;
                a[i][0] = A[(ko + tg) * SA2 + rb];
                a[i][1] = A[(ko + tg) * SA2 + rb + 8];
                a[i][2] = A[(ko + tg + 4) * SA2 + rb];
                a[i][3] = A[(ko + tg + 4) * SA2 + rb + 8];
            }
#pragma unroll
            for (int j = 0; j < 8; ++j) {
                const int cb = wn + j * 8 + g;
                uint32_t b0 = B[(ko + tg) * SB2 + cb];
                uint32_t b1 = B[(ko + tg + 4) * SB2 + cb];
#pragma unroll
                for (int i = 0; i < 2; ++i) mma16(acc[i][j], a[i], b0, b1);
            }
        }
        if (kc < NCH - 1) { ST_A(buf ^ 1); ST_B(buf ^ 1); }
        __syncthreads();
    }

    // ---- fused epilogue: sigmoid + pooled partials (unique slot per warp-col)
    const int slot = blockIdx.x * 2 + (wid & 1);
#pragma unroll
    for (int i = 0; i < 2; ++i) {
#pragma unroll
        for (int rs = 0; rs < 2; ++rs) {
            const int row = m0 + wm + i * 16 + g + rs * 8;
            const float* xr = xz + (size_t)row * HW + n0 + wn + 2 * tg;
            float sS = 0.0f, sP = 0.0f;
#pragma unroll
            for (int j = 0; j < 8; ++j) {
                float v0 = acc[i][j][2 * rs];
                float v1 = acc[i][j][2 * rs + 1];
                float s0 = __fdividef(1.0f, 1.0f + __expf(-v0));
                float s1 = __fdividef(1.0f, 1.0f + __expf(-v1));
                float2 xv = *(const float2*)(xr + j * 8);
                sS += s0 + s1;
                sP += s0 * xv.x + s1 * xv.y;
            }
            sS += __shfl_xor_sync(0xffffffffu, sS, 1);
            sS += __shfl_xor_sync(0xffffffffu, sS, 2);
            sP += __shfl_xor_sync(0xffffffffu, sP, 1);
            sP += __shfl_xor_sync(0xffffffffu, sP, 2);
            if (tg == 0) {
                g_S[z][slot][row] = sS;
                g_P[z][slot][row] = sP;
            }
        }
    }
}

// ---------------------------------------------------------------------------
__global__ void finalize_kernel(float* __restrict__ out) {
    int i = blockIdx.x * blockDim.x + threadIdx.x;
    if (i < Bsz * Csz) {
        int b = i >> 8, o = i & 255;
        float r = 0.0f;
#pragma unroll
        for (int br = 0; br < 2; ++br) {
            int z = br * Bsz + b;
            float S = 0.0f, P = 0.0f;
#pragma unroll
            for (int s = 0; s < 16; ++s) {
                S += g_S[z][s][o];
                P += g_P[z][s][o];
            }
            r += P / (S + 1e-8f);
        }
        out[i] = r;
    }
}

// ---------------------------------------------------------------------------
extern "C" void kernel_launch(void* const* d_in, const int* in_sizes, int n_in,
                              void* d_out, int out_size) {
    const float* x1 = (const float*)d_in[0];
    const float* x2 = (const float*)d_in[1];
    const float* w  = (const float*)d_in[2];
    // d_in[3..6] (ca_*) are mathematically unused: softmax over a size-1 axis == 1.
    float* out = (float*)d_out;

    constexpr int SMEM_SZ = (2 * 16 * SA2 + 2 * 16 * SB2) * 4;   // 34816 B
    cudaFuncSetAttribute(gemm_pool_kernel,
                         cudaFuncAttributeMaxDynamicSharedMemorySize, SMEM_SZ);

    transpose_w<<<257, 256>>>(w);
    build_wzh<<<dim3(32, 2 * Bsz), 1024>>>(x1, x2);
    gemm_pool_kernel<<<dim3(8, 2, 2 * Bsz), 256, SMEM_SZ>>>(x1, x2);
    finalize_kernel<<<(Bsz * Csz + 255) / 256, 256>>>(out);
}

// round 9
// speedup vs baseline: 4.3482x; 1.1236x over previous
#include <cuda_runtime.h>
#include <cuda_fp16.h>
#include <cstdint>

#define Bsz  64
#define Csz  256
#define HW   1024
#define CTR  528        // 16*32 + 16
#define KC   32         // K chunk (= 16 fp16x2 k-pairs)
#define NCH  8          // 256 / 32
#define SA2  136        // A smem k2-row stride (u32)
#define SB2  136        // B smem k2-row stride (u32)
#define BUFU (16 * SA2) // u32 per buffer (2176)

// per-CTA-per-warpcolumn partials: [z][ntile*2 + wncol][o]  (16 slots)
__device__ float g_S[2 * Bsz][16][Csz];
__device__ float g_P[2 * Bsz][16][Csz];

// transposed weights; per-z folded A operand packed as fp16x2 over k-pairs
__device__ float    g_Wt[257][Csz];
__device__ uint32_t g_Wzh[2 * Bsz][Csz / 2][Csz];   // 16.8 MB

__device__ __forceinline__ uint32_t packf16(float lo, float hi) {
    uint32_t d;
    asm("cvt.rn.f16x2.f32 %0, %1, %2;" : "=r"(d) : "f"(hi), "f"(lo));
    return d;
}

__device__ __forceinline__ void mma16(float* c, const uint32_t* a,
                                      uint32_t b0, uint32_t b1) {
    asm volatile(
        "mma.sync.aligned.m16n8k16.row.col.f32.f16.f16.f32 "
        "{%0,%1,%2,%3}, {%4,%5,%6,%7}, {%8,%9}, {%0,%1,%2,%3};"
        : "+f"(c[0]), "+f"(c[1]), "+f"(c[2]), "+f"(c[3])
        : "r"(a[0]), "r"(a[1]), "r"(a[2]), "r"(a[3]), "r"(b0), "r"(b1));
}

__device__ __forceinline__ uint32_t smem_u32(const void* p) {
    uint32_t a;
    asm("{ .reg .u64 t; cvta.to.shared.u64 t, %1; cvt.u32.u64 %0, t; }" : "=r"(a) : "l"(p));
    return a;
}

// ---------------------------------------------------------------------------
// prep 1: Wt[k][m] = W[m][k]
// ---------------------------------------------------------------------------
__global__ void transpose_w(const float* __restrict__ w) {
    int k = blockIdx.x;          // 0..256
    int m = threadIdx.x;         // 0..255
    g_Wt[k][m] = w[(size_t)m * 257 + k];
}

// ---------------------------------------------------------------------------
// prep 2: Wzh[z][k2][m] = fp16x2 of the two folded k values
// ---------------------------------------------------------------------------
__global__ void __launch_bounds__(1024) build_wzh(const float* __restrict__ x1,
                                                  const float* __restrict__ x2) {
    const int z = blockIdx.y;
    const int branch = z >> 6, b = z & 63;
    const float* xz = (branch ? x2 : x1) + (size_t)b * Csz * HW;

    int idx = blockIdx.x * 1024 + threadIdx.x;
    int m = idx & 255;
    int k2 = idx >> 8;                            // 0..127
    float cen0 = xz[(size_t)(2 * k2) * HW + CTR] * (1.0f / 256.0f);
    float cen1 = xz[(size_t)(2 * k2 + 1) * HW + CTR] * (1.0f / 256.0f);
    float wc = g_Wt[256][m];
    float v0 = g_Wt[2 * k2][m] + wc * cen0;
    float v1 = g_Wt[2 * k2 + 1][m] + wc * cen1;
    g_Wzh[z][k2][m] = packf16(v0, v1);
}

// ---------------------------------------------------------------------------
// main GEMM (fp16 in, fp32 acc) + fused sigmoid-pool
// grid (8 n-tiles, 2 m-tiles, 128 z), block 256 (8 warps = 4M x 2N, 32x64 each)
// 2 CTAs/SM. A staged via cp.async; B chunks overlapping the m-tile are
// stashed in smem so the epilogue never touches global x again.
// ---------------------------------------------------------------------------
__global__ void __launch_bounds__(256, 2)
gemm_pool_kernel(const float* __restrict__ x1, const float* __restrict__ x2) {
    extern __shared__ uint32_t sm[];
    uint32_t* Ab[2] = { sm, sm + BUFU };
    uint32_t* Bb[2] = { sm + 2 * BUFU, sm + 3 * BUFU };
    uint32_t* stash = sm + 4 * BUFU;              // 64 k2-rows x SB2

    const int tid = threadIdx.x;
    const int z = blockIdx.z;
    const int branch = z >> 6, b = z & 63;
    const float* xz = (branch ? x2 : x1) + (size_t)b * Csz * HW;
    const int m0 = blockIdx.y * 128;
    const int n0 = blockIdx.x * 128;
    const uint32_t* wzh = &g_Wzh[z][0][0];        // [128 k2][256 m]

    const uint32_t sA0 = smem_u32(Ab[0]);
    const uint32_t sA1 = smem_u32(Ab[1]);

    float4 Brf[2][2];

    // A: 2 x 16B cp.async/thread: idx = tid + q*256 -> k2 = idx>>5, m4=(idx&31)*4
#define CPA(kc, sbase) { _Pragma("unroll") for (int q = 0; q < 2; ++q) {       \
        int idx = tid + q * 256;                                               \
        uint32_t dst = (sbase) + ((idx >> 5) * SA2 + (idx & 31) * 4) * 4;      \
        const uint32_t* src = wzh + (size_t)((kc) * 16 + (idx >> 5)) * 256     \
                              + m0 + (idx & 31) * 4;                           \
        asm volatile("cp.async.cg.shared.global [%0], [%1], 16;"               \
                     :: "r"(dst), "l"(src)); }                                 \
    asm volatile("cp.async.commit_group;"); }
    // B: 2 k-rows packed per u32; idx = tid + q*256: k2 = idx>>5, n4=(idx&31)*4
#define LD_B(kc) { _Pragma("unroll") for (int q = 0; q < 2; ++q) {             \
        int idx = tid + q * 256;                                               \
        const float* p0 = xz + (size_t)((kc) * KC + 2 * (idx >> 5)) * HW       \
                          + n0 + (idx & 31) * 4;                               \
        Brf[q][0] = *(const float4*)p0;                                        \
        Brf[q][1] = *(const float4*)(p0 + HW); } }
    // store B chunk kc into buffer; stash the 4 chunks covering [m0, m0+128)
#define ST_B(buf, kc) { const int dostash = ((kc) >> 2) == blockIdx.y;         \
    const int srow = ((kc) & 3) * 16;                                          \
    _Pragma("unroll") for (int q = 0; q < 2; ++q) {                            \
        int idx = tid + q * 256;                                               \
        uint4 v;                                                               \
        v.x = packf16(Brf[q][0].x, Brf[q][1].x);                               \
        v.y = packf16(Brf[q][0].y, Brf[q][1].y);                               \
        v.z = packf16(Brf[q][0].z, Brf[q][1].z);                               \
        v.w = packf16(Brf[q][0].w, Brf[q][1].w);                               \
        *(uint4*)(Bb[buf] + (idx >> 5) * SB2 + (idx & 31) * 4) = v;            \
        if (dostash)                                                           \
            *(uint4*)(stash + (srow + (idx >> 5)) * SB2 + (idx & 31) * 4) = v; } }

    // ---- MMA mapping: 8 warps = 4 (M) x 2 (N); warp tile 32 x 64
    const int lane = tid & 31;
    const int wid = tid >> 5;
    const int wm = (wid >> 1) * 32;
    const int wn = (wid & 1) * 64;
    const int g = lane >> 2, tg = lane & 3;

    float acc[2][8][4];
#pragma unroll
    for (int i = 0; i < 2; ++i)
#pragma unroll
        for (int j = 0; j < 8; ++j)
#pragma unroll
            for (int r = 0; r < 4; ++r) acc[i][j][r] = 0.0f;

    CPA(0, sA0); LD_B(0); ST_B(0, 0);
    asm volatile("cp.async.wait_group 0;");
    __syncthreads();

    for (int kc = 0; kc < NCH; ++kc) {
        const int buf = kc & 1;
        if (kc < NCH - 1) { CPA(kc + 1, buf ? sA0 : sA1); LD_B(kc + 1); }

        const uint32_t* A = Ab[buf];
        const uint32_t* B = Bb[buf];
#pragma unroll
        for (int ks = 0; ks < 2; ++ks) {
            const int ko = ks * 8;                 // k2 offset (8 pairs = k16)
            uint32_t a[2][4];
#pragma unroll
            for (int i = 0; i < 2; ++i) {
                const int rb = wm + i * 16 + g;
                a[i][0] = A[(ko + tg) * SA2 + rb];
                a[i][1] = A[(ko + tg) * SA2 + rb + 8];
                a[i][2] = A[(ko + tg + 4) * SA2 + rb];
                a[i][3] = A[(ko + tg + 4) * SA2 + rb + 8];
            }
#pragma unroll
            for (int j = 0; j < 8; ++j) {
                const int cb = wn + j * 8 + g;
                uint32_t b0 = B[(ko + tg) * SB2 + cb];
                uint32_t b1 = B[(ko + tg + 4) * SB2 + cb];
#pragma unroll
                for (int i = 0; i < 2; ++i) mma16(acc[i][j], a[i], b0, b1);
            }
        }
        if (kc < NCH - 1) {
            ST_B(buf ^ 1, kc + 1);
            asm volatile("cp.async.wait_group 0;");
        }
        __syncthreads();
    }

    // ---- fused epilogue: sigmoid + pooled partials; x read from fp16 stash
    const int slot = blockIdx.x * 2 + (wid & 1);
#pragma unroll
    for (int i = 0; i < 2; ++i) {
#pragma unroll
        for (int rs = 0; rs < 2; ++rs) {
            const int lrow = wm + i * 16 + g + rs * 8;      // 0..127
            const int k2L = lrow >> 1, h = lrow & 1;
            const uint32_t* srow = stash + k2L * SB2 + wn + 2 * tg;
            float sS = 0.0f, sP = 0.0f;
#pragma unroll
            for (int j = 0; j < 8; ++j) {
                uint2 u = *(const uint2*)(srow + j * 8);
                __half2 p0 = *reinterpret_cast<__half2*>(&u.x);
                __half2 p1 = *reinterpret_cast<__half2*>(&u.y);
                float xv0 = h ? __high2float(p0) : __low2float(p0);
                float xv1 = h ? __high2float(p1) : __low2float(p1);
                float v0 = acc[i][j][2 * rs];
                float v1 = acc[i][j][2 * rs + 1];
                float s0 = __fdividef(1.0f, 1.0f + __expf(-v0));
                float s1 = __fdividef(1.0f, 1.0f + __expf(-v1));
                sS += s0 + s1;
                sP += s0 * xv0 + s1 * xv1;
            }
            sS += __shfl_xor_sync(0xffffffffu, sS, 1);
            sS += __shfl_xor_sync(0xffffffffu, sS, 2);
            sP += __shfl_xor_sync(0xffffffffu, sP, 1);
            sP += __shfl_xor_sync(0xffffffffu, sP, 2);
            if (tg == 0) {
                g_S[z][slot][m0 + lrow] = sS;
                g_P[z][slot][m0 + lrow] = sP;
            }
        }
    }
}

// ---------------------------------------------------------------------------
__global__ void finalize_kernel(float* __restrict__ out) {
    int i = blockIdx.x * blockDim.x + threadIdx.x;
    if (i < Bsz * Csz) {
        int b = i >> 8, o = i & 255;
        float r = 0.0f;
#pragma unroll
        for (int br = 0; br < 2; ++br) {
            int z = br * Bsz + b;
            float S = 0.0f, P = 0.0f;
#pragma unroll
            for (int s = 0; s < 16; ++s) {
                S += g_S[z][s][o];
                P += g_P[z][s][o];
            }
            r += P / (S + 1e-8f);
        }
        out[i] = r;
    }
}

// ---------------------------------------------------------------------------
extern "C" void kernel_launch(void* const* d_in, const int* in_sizes, int n_in,
                              void* d_out, int out_size) {
    const float* x1 = (const float*)d_in[0];
    const float* x2 = (const float*)d_in[1];
    const float* w  = (const float*)d_in[2];
    // d_in[3..6] (ca_*) are mathematically unused: softmax over a size-1 axis == 1.
    float* out = (float*)d_out;

    constexpr int SMEM_SZ = (4 * BUFU + 64 * SB2) * 4;   // 69632 B
    cudaFuncSetAttribute(gemm_pool_kernel,
                         cudaFuncAttributeMaxDynamicSharedMemorySize, SMEM_SZ);

    transpose_w<<<257, 256>>>(w);
    build_wzh<<<dim3(32, 2 * Bsz), 1024>>>(x1, x2);
    gemm_pool_kernel<<<dim3(8, 2, 2 * Bsz), 256, SMEM_SZ>>>(x1, x2);
    finalize_kernel<<<(Bsz * Csz + 255) / 256, 256>>>(out);
}

// round 10
// speedup vs baseline: 4.7006x; 1.0810x over previous
#include <cuda_runtime.h>
#include <cuda_fp16.h>
#include <cstdint>

#define Bsz  64
#define Csz  256
#define HW   1024
#define CTR  528        // 16*32 + 16
#define KC   32         // K chunk (= 16 fp16x2 k-pairs)
#define NCH  8          // 256 / 32
#define SA2  136        // A smem k2-row stride (u32)
#define SB2  136        // B smem k2-row stride (u32)
#define BUFU (16 * SA2) // u32 per buffer (2176)

// per-CTA partials: [z][ntile][o]  (8 slots; N-warp-columns pre-reduced in smem)
__device__ float g_S[2 * Bsz][8][Csz];
__device__ float g_P[2 * Bsz][8][Csz];

// transposed weights; per-z folded A operand packed as fp16x2 over k-pairs
__device__ float    g_Wt[257][Csz];
__device__ uint32_t g_Wzh[2 * Bsz][Csz / 2][Csz];   // 16.8 MB

__device__ __forceinline__ uint32_t packf16(float lo, float hi) {
    uint32_t d;
    asm("cvt.rn.f16x2.f32 %0, %1, %2;" : "=r"(d) : "f"(hi), "f"(lo));
    return d;
}

__device__ __forceinline__ void mma16(float* c, const uint32_t* a,
                                      uint32_t b0, uint32_t b1) {
    asm volatile(
        "mma.sync.aligned.m16n8k16.row.col.f32.f16.f16.f32 "
        "{%0,%1,%2,%3}, {%4,%5,%6,%7}, {%8,%9}, {%0,%1,%2,%3};"
        : "+f"(c[0]), "+f"(c[1]), "+f"(c[2]), "+f"(c[3])
        : "r"(a[0]), "r"(a[1]), "r"(a[2]), "r"(a[3]), "r"(b0), "r"(b1));
}

__device__ __forceinline__ uint32_t smem_u32(const void* p) {
    uint32_t a;
    asm("{ .reg .u64 t; cvta.to.shared.u64 t, %1; cvt.u32.u64 %0, t; }" : "=r"(a) : "l"(p));
    return a;
}

// ---------------------------------------------------------------------------
// prep 1: Wt[k][m] = W[m][k]
// ---------------------------------------------------------------------------
__global__ void transpose_w(const float* __restrict__ w) {
    int k = blockIdx.x;          // 0..256
    int m = threadIdx.x;         // 0..255
    g_Wt[k][m] = w[(size_t)m * 257 + k];
}

// ---------------------------------------------------------------------------
// prep 2: Wzh[z][k2][m] = fp16x2 of the two folded k values
// ---------------------------------------------------------------------------
__global__ void __launch_bounds__(1024) build_wzh(const float* __restrict__ x1,
                                                  const float* __restrict__ x2) {
    const int z = blockIdx.y;
    const int branch = z >> 6, b = z & 63;
    const float* xz = (branch ? x2 : x1) + (size_t)b * Csz * HW;

    int idx = blockIdx.x * 1024 + threadIdx.x;
    int m = idx & 255;
    int k2 = idx >> 8;                            // 0..127
    float cen0 = xz[(size_t)(2 * k2) * HW + CTR] * (1.0f / 256.0f);
    float cen1 = xz[(size_t)(2 * k2 + 1) * HW + CTR] * (1.0f / 256.0f);
    float wc = g_Wt[256][m];
    float v0 = g_Wt[2 * k2][m] + wc * cen0;
    float v1 = g_Wt[2 * k2 + 1][m] + wc * cen1;
    g_Wzh[z][k2][m] = packf16(v0, v1);
}

// ---------------------------------------------------------------------------
// main GEMM (fp16 in, fp32 acc) + fused sigmoid-pool
// grid (8 n-tiles, 2 m-tiles, 128 z), block 256 (8 warps = 4M x 2N, 32x64 each)
// 2 CTAs/SM. A via cp.async; m-tile-overlapping B chunks stashed for epilogue.
// ---------------------------------------------------------------------------
__global__ void __launch_bounds__(256, 2)
gemm_pool_kernel(const float* __restrict__ x1, const float* __restrict__ x2) {
    extern __shared__ uint32_t sm[];
    uint32_t* Ab[2] = { sm, sm + BUFU };
    uint32_t* Bb[2] = { sm + 2 * BUFU, sm + 3 * BUFU };
    uint32_t* stash = sm + 4 * BUFU;              // 64 k2-rows x SB2
    float* red = (float*)sm;                      // reuse A buffers post-loop

    const int tid = threadIdx.x;
    const int z = blockIdx.z;
    const int branch = z >> 6, b = z & 63;
    const float* xz = (branch ? x2 : x1) + (size_t)b * Csz * HW;
    const int m0 = blockIdx.y * 128;
    const int n0 = blockIdx.x * 128;
    const uint32_t* wzh = &g_Wzh[z][0][0];        // [128 k2][256 m]

    const uint32_t sA0 = smem_u32(Ab[0]);
    const uint32_t sA1 = smem_u32(Ab[1]);

    float4 Brf[2][2];

#define CPA(kc, sbase) { _Pragma("unroll") for (int q = 0; q < 2; ++q) {       \
        int idx = tid + q * 256;                                               \
        uint32_t dst = (sbase) + ((idx >> 5) * SA2 + (idx & 31) * 4) * 4;      \
        const uint32_t* src = wzh + (size_t)((kc) * 16 + (idx >> 5)) * 256     \
                              + m0 + (idx & 31) * 4;                           \
        asm volatile("cp.async.cg.shared.global [%0], [%1], 16;"               \
                     :: "r"(dst), "l"(src)); }                                 \
    asm volatile("cp.async.commit_group;"); }
#define LD_B(kc) { _Pragma("unroll") for (int q = 0; q < 2; ++q) {             \
        int idx = tid + q * 256;                                               \
        const float* p0 = xz + (size_t)((kc) * KC + 2 * (idx >> 5)) * HW       \
                          + n0 + (idx & 31) * 4;                               \
        Brf[q][0] = *(const float4*)p0;                                        \
        Brf[q][1] = *(const float4*)(p0 + HW); } }
#define ST_B(buf, kc) { const int dostash = ((kc) >> 2) == blockIdx.y;         \
    const int srow = ((kc) & 3) * 16;                                          \
    _Pragma("unroll") for (int q = 0; q < 2; ++q) {                            \
        int idx = tid + q * 256;                                               \
        uint4 v;                                                               \
        v.x = packf16(Brf[q][0].x, Brf[q][1].x);                               \
        v.y = packf16(Brf[q][0].y, Brf[q][1].y);                               \
        v.z = packf16(Brf[q][0].z, Brf[q][1].z);                               \
        v.w = packf16(Brf[q][0].w, Brf[q][1].w);                               \
        *(uint4*)(Bb[buf] + (idx >> 5) * SB2 + (idx & 31) * 4) = v;            \
        if (dostash)                                                           \
            *(uint4*)(stash + (srow + (idx >> 5)) * SB2 + (idx & 31) * 4) = v; } }

    // ---- MMA mapping: 8 warps = 4 (M) x 2 (N); warp tile 32 x 64
    const int lane = tid & 31;
    const int wid = tid >> 5;
    const int wm = (wid >> 1) * 32;
    const int wn = (wid & 1) * 64;
    const int g = lane >> 2, tg = lane & 3;

    float acc[2][8][4];
#pragma unroll
    for (int i = 0; i < 2; ++i)
#pragma unroll
        for (int j = 0; j < 8; ++j)
#pragma unroll
            for (int r = 0; r < 4; ++r) acc[i][j][r] = 0.0f;

    CPA(0, sA0); LD_B(0); ST_B(0, 0);
    asm volatile("cp.async.wait_group 0;");
    __syncthreads();

#pragma unroll
    for (int kc = 0; kc < NCH; ++kc) {
        const int buf = kc & 1;
        if (kc < NCH - 1) { CPA(kc + 1, buf ? sA0 : sA1); LD_B(kc + 1); }

        const uint32_t* A = Ab[buf];
        const uint32_t* B = Bb[buf];
#pragma unroll
        for (int ks = 0; ks < 2; ++ks) {
            const int ko = ks * 8;                 // k2 offset (8 pairs = k16)
            uint32_t a[2][4];
#pragma unroll
            for (int i = 0; i < 2; ++i) {
                const int rb = wm + i * 16 + g;
                a[i][0] = A[(ko + tg) * SA2 + rb];
                a[i][1] = A[(ko + tg) * SA2 + rb + 8];
                a[i][2] = A[(ko + tg + 4) * SA2 + rb];
                a[i][3] = A[(ko + tg + 4) * SA2 + rb + 8];
            }
#pragma unroll
            for (int j = 0; j < 8; ++j) {
                const int cb = wn + j * 8 + g;
                uint32_t b0 = B[(ko + tg) * SB2 + cb];
                uint32_t b1 = B[(ko + tg + 4) * SB2 + cb];
#pragma unroll
                for (int i = 0; i < 2; ++i) mma16(acc[i][j], a[i], b0, b1);
            }
        }
        if (kc < NCH - 1) {
            ST_B(buf ^ 1, kc + 1);
            asm volatile("cp.async.wait_group 0;");
        }
        __syncthreads();
    }

    // ---- fused epilogue: sigmoid + pooled partials; x from fp16 stash;
    //      N-warp-columns combined via smem -> 8 slots total
    const int wnc = wid & 1;
#pragma unroll
    for (int i = 0; i < 2; ++i) {
#pragma unroll
        for (int rs = 0; rs < 2; ++rs) {
            const int lrow = wm + i * 16 + g + rs * 8;      // 0..127
            const int k2L = lrow >> 1, h = lrow & 1;
            const uint32_t* srow = stash + k2L * SB2 + wn + 2 * tg;
            float sS = 0.0f, sP = 0.0f;
#pragma unroll
            for (int j = 0; j < 8; ++j) {
                uint2 u = *(const uint2*)(srow + j * 8);
                __half2 p0 = *reinterpret_cast<__half2*>(&u.x);
                __half2 p1 = *reinterpret_cast<__half2*>(&u.y);
                float xv0 = h ? __high2float(p0) : __low2float(p0);
                float xv1 = h ? __high2float(p1) : __low2float(p1);
                float v0 = acc[i][j][2 * rs];
                float v1 = acc[i][j][2 * rs + 1];
                float s0 = __fdividef(1.0f, 1.0f + __expf(-v0));
                float s1 = __fdividef(1.0f, 1.0f + __expf(-v1));
                sS += s0 + s1;
                sP += s0 * xv0 + s1 * xv1;
            }
            sS += __shfl_xor_sync(0xffffffffu, sS, 1);
            sS += __shfl_xor_sync(0xffffffffu, sS, 2);
            sP += __shfl_xor_sync(0xffffffffu, sP, 1);
            sP += __shfl_xor_sync(0xffffffffu, sP, 2);
            if (tg == 0) {
                red[lrow * 4 + wnc] = sS;        // [128 rows][2 cols S][2 cols P]
                red[lrow * 4 + 2 + wnc] = sP;
            }
        }
    }
    __syncthreads();
    if (tid < 128) {
        float S = red[tid * 4 + 0] + red[tid * 4 + 1];
        float P = red[tid * 4 + 2] + red[tid * 4 + 3];
        g_S[z][blockIdx.x][m0 + tid] = S;
        g_P[z][blockIdx.x][m0 + tid] = P;
    }
}

// ---------------------------------------------------------------------------
// finalize: 8 threads per output; per-branch divide, then cross-branch add.
// grid 512 x block 256 -> 32 outputs/block
// ---------------------------------------------------------------------------
__global__ void finalize_kernel(float* __restrict__ out) {
    const int tid = threadIdx.x;
    const int i = blockIdx.x * 32 + (tid >> 3);   // output index (b*256+o)
    const int part = tid & 7;                      // br = part>>2, spair = part&3
    const int b = i >> 8, o = i & 255;
    const int br = part >> 2;
    const int z = br * Bsz + b;
    const int s0 = (part & 3) * 2;

    float S = g_S[z][s0][o] + g_S[z][s0 + 1][o];
    float P = g_P[z][s0][o] + g_P[z][s0 + 1][o];
    // reduce the 4 s-parts within each branch (lanes differ in bits 0..1)
    S += __shfl_xor_sync(0xffffffffu, S, 1);
    P += __shfl_xor_sync(0xffffffffu, P, 1);
    S += __shfl_xor_sync(0xffffffffu, S, 2);
    P += __shfl_xor_sync(0xffffffffu, P, 2);
    float r = P / (S + 1e-8f);
    // add the two branches (lanes differ in bit 2)
    r += __shfl_xor_sync(0xffffffffu, r, 4);
    if (part == 0) out[i] = r;
}

// ---------------------------------------------------------------------------
extern "C" void kernel_launch(void* const* d_in, const int* in_sizes, int n_in,
                              void* d_out, int out_size) {
    const float* x1 = (const float*)d_in[0];
    const float* x2 = (const float*)d_in[1];
    const float* w  = (const float*)d_in[2];
    // d_in[3..6] (ca_*) are mathematically unused: softmax over a size-1 axis == 1.
    float* out = (float*)d_out;

    constexpr int SMEM_SZ = (4 * BUFU + 64 * SB2) * 4;   // 69632 B
    cudaFuncSetAttribute(gemm_pool_kernel,
                         cudaFuncAttributeMaxDynamicSharedMemorySize, SMEM_SZ);

    transpose_w<<<257, 256>>>(w);
    build_wzh<<<dim3(32, 2 * Bsz), 1024>>>(x1, x2);
    gemm_pool_kernel<<<dim3(8, 2, 2 * Bsz), 256, SMEM_SZ>>>(x1, x2);
    finalize_kernel<<<512, 256>>>(out);
}

// round 11
// speedup vs baseline: 4.8219x; 1.0258x over previous
#include <cuda_runtime.h>
#include <cuda_fp16.h>
#include <cstdint>

#define Bsz  64
#define Csz  256
#define HW   1024
#define CTR  528        // 16*32 + 16
#define KC   32         // K chunk (= 16 fp16x2 k-pairs)
#define NCH  8          // 256 / 32
#define SA2  264        // A smem k2-row stride (u32): 256 + 8
#define SB2  72         // B smem k2-row stride (u32): 64 + 8
#define BUFA (16 * SA2) // 4224 u32
#define BUFB (16 * SB2) // 1152 u32

// per-CTA partials: [z][ntile][o]  (16 n-tiles; each row fully reduced in-warp)
__device__ float g_S[2 * Bsz][16][Csz];
__device__ float g_P[2 * Bsz][16][Csz];

// transposed weights; per-z folded A operand packed as fp16x2 over k-pairs
__device__ float    g_Wt[257][Csz];
__device__ uint32_t g_Wzh[2 * Bsz][Csz / 2][Csz];   // 16.8 MB (L2-resident)

__device__ __forceinline__ uint32_t packf16(float lo, float hi) {
    uint32_t d;
    asm("cvt.rn.f16x2.f32 %0, %1, %2;" : "=r"(d) : "f"(hi), "f"(lo));
    return d;
}

__device__ __forceinline__ void mma16(float* c, const uint32_t* a,
                                      uint32_t b0, uint32_t b1) {
    asm volatile(
        "mma.sync.aligned.m16n8k16.row.col.f32.f16.f16.f32 "
        "{%0,%1,%2,%3}, {%4,%5,%6,%7}, {%8,%9}, {%0,%1,%2,%3};"
        : "+f"(c[0]), "+f"(c[1]), "+f"(c[2]), "+f"(c[3])
        : "r"(a[0]), "r"(a[1]), "r"(a[2]), "r"(a[3]), "r"(b0), "r"(b1));
}

__device__ __forceinline__ uint32_t smem_u32(const void* p) {
    uint32_t a;
    asm("{ .reg .u64 t; cvta.to.shared.u64 t, %1; cvt.u32.u64 %0, t; }" : "=r"(a) : "l"(p));
    return a;
}

// ---------------------------------------------------------------------------
// prep 1: Wt[k][m] = W[m][k]
// ---------------------------------------------------------------------------
__global__ void transpose_w(const float* __restrict__ w) {
    int k = blockIdx.x;          // 0..256
    int m = threadIdx.x;         // 0..255
    g_Wt[k][m] = w[(size_t)m * 257 + k];
}

// ---------------------------------------------------------------------------
// prep 2: Wzh[z][k2][m] = fp16x2 of the two folded k values
// ---------------------------------------------------------------------------
__global__ void __launch_bounds__(1024) build_wzh(const float* __restrict__ x1,
                                                  const float* __restrict__ x2) {
    const int z = blockIdx.y;
    const int branch = z >> 6, b = z & 63;
    const float* xz = (branch ? x2 : x1) + (size_t)b * Csz * HW;

    int idx = blockIdx.x * 1024 + threadIdx.x;
    int m = idx & 255;
    int k2 = idx >> 8;                            // 0..127
    float cen0 = xz[(size_t)(2 * k2) * HW + CTR] * (1.0f / 256.0f);
    float cen1 = xz[(size_t)(2 * k2 + 1) * HW + CTR] * (1.0f / 256.0f);
    float wc = g_Wt[256][m];
    float v0 = g_Wt[2 * k2][m] + wc * cen0;
    float v1 = g_Wt[2 * k2 + 1][m] + wc * cen1;
    g_Wzh[z][k2][m] = packf16(v0, v1);
}

// ---------------------------------------------------------------------------
// main GEMM (fp16 in, fp32 acc) + fused sigmoid-pool
// grid (16 n-tiles, 128 z), block 256 (8 warps = 8M x 1N; warp tile 32 x 64)
// M=256 (full C) x N=64 per CTA -> x read ONCE per z (LTS relief).
// All B chunks stashed in smem; epilogue never touches global x.
// ---------------------------------------------------------------------------
__global__ void __launch_bounds__(256, 2)
gemm_pool_kernel(const float* __restrict__ x1, const float* __restrict__ x2) {
    extern __shared__ uint32_t sm[];
    uint32_t* Ab[2] = { sm, sm + BUFA };
    uint32_t* Bb[2] = { sm + 2 * BUFA, sm + 2 * BUFA + BUFB };
    uint32_t* stash = sm + 2 * BUFA + 2 * BUFB;   // 128 k2-rows x SB2

    const int tid = threadIdx.x;
    const int z = blockIdx.y;
    const int branch = z >> 6, b = z & 63;
    const float* xz = (branch ? x2 : x1) + (size_t)b * Csz * HW;
    const int n0 = blockIdx.x * 64;
    const uint32_t* wzh = &g_Wzh[z][0][0];        // [128 k2][256 m]

    const uint32_t sA0 = smem_u32(Ab[0]);
    const uint32_t sA1 = smem_u32(Ab[1]);

    float4 Brf0, Brf1;

    // A: 4 x 16B cp.async/thread: idx = tid + q*256 -> k2 = idx>>6, m4=(idx&63)*4
#define CPA(kc, sbase) { _Pragma("unroll") for (int q = 0; q < 4; ++q) {       \
        int idx = tid + q * 256;                                               \
        uint32_t dst = (sbase) + ((idx >> 6) * SA2 + (idx & 63) * 4) * 4;      \
        const uint32_t* src = wzh + (size_t)((kc) * 16 + (idx >> 6)) * 256     \
                              + (idx & 63) * 4;                                \
        asm volatile("cp.async.cg.shared.global [%0], [%1], 16;"               \
                     :: "r"(dst), "l"(src)); }                                 \
    asm volatile("cp.async.commit_group;"); }
    // B: 2 k-rows packed per u32: row = tid>>4 (16 k2-rows), n4 = (tid&15)*4
#define LD_B(kc) {                                                             \
        const float* p0 = xz + (size_t)((kc) * KC + 2 * (tid >> 4)) * HW       \
                          + n0 + (tid & 15) * 4;                               \
        Brf0 = *(const float4*)p0;                                             \
        Brf1 = *(const float4*)(p0 + HW); }
#define ST_B(buf, kc) {                                                        \
        uint4 v;                                                               \
        v.x = packf16(Brf0.x, Brf1.x);                                         \
        v.y = packf16(Brf0.y, Brf1.y);                                         \
        v.z = packf16(Brf0.z, Brf1.z);                                         \
        v.w = packf16(Brf0.w, Brf1.w);                                         \
        *(uint4*)(Bb[buf] + (tid >> 4) * SB2 + (tid & 15) * 4) = v;            \
        *(uint4*)(stash + ((kc) * 16 + (tid >> 4)) * SB2 + (tid & 15) * 4) = v; }

    // ---- MMA mapping: 8 warps stacked in M; warp tile 32 x 64
    const int lane = tid & 31;
    const int wid = tid >> 5;
    const int wm = wid * 32;
    const int g = lane >> 2, tg = lane & 3;

    float acc[2][8][4];
#pragma unroll
    for (int i = 0; i < 2; ++i)
#pragma unroll
        for (int j = 0; j < 8; ++j)
#pragma unroll
            for (int r = 0; r < 4; ++r) acc[i][j][r] = 0.0f;

    CPA(0, sA0); LD_B(0); ST_B(0, 0);
    asm volatile("cp.async.wait_group 0;");
    __syncthreads();

#pragma unroll
    for (int kc = 0; kc < NCH; ++kc) {
        const int buf = kc & 1;
        if (kc < NCH - 1) { CPA(kc + 1, buf ? sA0 : sA1); LD_B(kc + 1); }

        const uint32_t* A = Ab[buf];
        const uint32_t* B = Bb[buf];
#pragma unroll
        for (int ks = 0; ks < 2; ++ks) {
            const int ko = ks * 8;                 // k2 offset (8 pairs = k16)
            uint32_t a[2][4];
#pragma unroll
            for (int i = 0; i < 2; ++i) {
                const int rb = wm + i * 16 + g;
                a[i][0] = A[(ko + tg) * SA2 + rb];
                a[i][1] = A[(ko + tg) * SA2 + rb + 8];
                a[i][2] = A[(ko + tg + 4) * SA2 + rb];
                a[i][3] = A[(ko + tg + 4) * SA2 + rb + 8];
            }
#pragma unroll
            for (int j = 0; j < 8; ++j) {
                const int cb = j * 8 + g;
                uint32_t b0 = B[(ko + tg) * SB2 + cb];
                uint32_t b1 = B[(ko + tg + 4) * SB2 + cb];
#pragma unroll
                for (int i = 0; i < 2; ++i) mma16(acc[i][j], a[i], b0, b1);
            }
        }
        if (kc < NCH - 1) {
            ST_B(buf ^ 1, kc + 1);
            asm volatile("cp.async.wait_group 0;");
        }
        __syncthreads();
    }

    // ---- fused epilogue: sigmoid + pooled partials; x from fp16 stash.
    // Each warp owns complete rows -> tg-shfl gives the full n-tile sum.
#pragma unroll
    for (int i = 0; i < 2; ++i) {
#pragma unroll
        for (int rs = 0; rs < 2; ++rs) {
            const int lrow = wm + i * 16 + g + rs * 8;      // 0..255
            const int k2L = lrow >> 1, h = lrow & 1;
            const uint32_t* srow = stash + k2L * SB2 + 2 * tg;
            float sS = 0.0f, sP = 0.0f;
#pragma unroll
            for (int j = 0; j < 8; ++j) {
                uint2 u = *(const uint2*)(srow + j * 8);
                __half2 p0 = *reinterpret_cast<__half2*>(&u.x);
                __half2 p1 = *reinterpret_cast<__half2*>(&u.y);
                float xv0 = h ? __high2float(p0) : __low2float(p0);
                float xv1 = h ? __high2float(p1) : __low2float(p1);
                float v0 = acc[i][j][2 * rs];
                float v1 = acc[i][j][2 * rs + 1];
                float s0 = __fdividef(1.0f, 1.0f + __expf(-v0));
                float s1 = __fdividef(1.0f, 1.0f + __expf(-v1));
                sS += s0 + s1;
                sP += s0 * xv0 + s1 * xv1;
            }
            sS += __shfl_xor_sync(0xffffffffu, sS, 1);
            sS += __shfl_xor_sync(0xffffffffu, sS, 2);
            sP += __shfl_xor_sync(0xffffffffu, sP, 1);
            sP += __shfl_xor_sync(0xffffffffu, sP, 2);
            if (tg == 0) {
                g_S[z][blockIdx.x][lrow] = sS;
                g_P[z][blockIdx.x][lrow] = sP;
            }
        }
    }
}

// ---------------------------------------------------------------------------
// finalize: 8 threads per output; per-branch divide, then cross-branch add.
// grid 512 x block 256 -> 32 outputs/block; 16 slots per (z, o)
// ---------------------------------------------------------------------------
__global__ void finalize_kernel(float* __restrict__ out) {
    const int tid = threadIdx.x;
    const int i = blockIdx.x * 32 + (tid >> 3);   // output index (b*256+o)
    const int part = tid & 7;                      // br = part>>2, quarter = part&3
    const int b = i >> 8, o = i & 255;
    const int br = part >> 2;
    const int z = br * Bsz + b;
    const int s0 = (part & 3) * 4;

    float S = (g_S[z][s0][o] + g_S[z][s0 + 1][o])
            + (g_S[z][s0 + 2][o] + g_S[z][s0 + 3][o]);
    float P = (g_P[z][s0][o] + g_P[z][s0 + 1][o])
            + (g_P[z][s0 + 2][o] + g_P[z][s0 + 3][o]);
    // reduce the 4 quarters within each branch (lanes differ in bits 0..1)
    S += __shfl_xor_sync(0xffffffffu, S, 1);
    P += __shfl_xor_sync(0xffffffffu, P, 1);
    S += __shfl_xor_sync(0xffffffffu, S, 2);
    P += __shfl_xor_sync(0xffffffffu, P, 2);
    float r = P / (S + 1e-8f);
    // add the two branches (lanes differ in bit 2)
    r += __shfl_xor_sync(0xffffffffu, r, 4);
    if (part == 0) out[i] = r;
}

// ---------------------------------------------------------------------------
extern "C" void kernel_launch(void* const* d_in, const int* in_sizes, int n_in,
                              void* d_out, int out_size) {
    const float* x1 = (const float*)d_in[0];
    const float* x2 = (const float*)d_in[1];
    const float* w  = (const float*)d_in[2];
    // d_in[3..6] (ca_*) are mathematically unused: softmax over a size-1 axis == 1.
    float* out = (float*)d_out;

    constexpr int SMEM_SZ = (2 * BUFA + 2 * BUFB + 128 * SB2) * 4;   // 79872 B
    cudaFuncSetAttribute(gemm_pool_kernel,
                         cudaFuncAttributeMaxDynamicSharedMemorySize, SMEM_SZ);

    transpose_w<<<257, 256>>>(w);
    build_wzh<<<dim3(32, 2 * Bsz), 1024>>>(x1, x2);
    gemm_pool_kernel<<<dim3(16, 2 * Bsz), 256, SMEM_SZ>>>(x1, x2);
    finalize_kernel<<<512, 256>>>(out);
}